// round 16
// baseline (speedup 1.0000x reference)
#include <cuda_runtime.h>
#include <cstdint>

#define NN 8192
#define DD 64
#define EPSF 1e-6f
#define PITCH_W 36   // 32-bit words per smem row (144B): conflict-free frags
#define T_U 0.0625f
#define L2E 1.44269504f
#define LN2 0.69314718f
#define SQRT2_L2E 2.04027891f   // sqrt(2) * log2(e)

// scratch (no allocations allowed)
__device__ double g_acc;
__device__ float g_pi[NN];    // 0.5*(sq + 2*eps*s + D*eps^2)
__device__ float g_qa[NN*2];  // interleaved: (0.5*(sq - 2*eps*s), alpha*log2e)

// ---------------------------------------------------------------------------
__global__ void prep_kernel(const float* __restrict__ Z,
                            const float* __restrict__ alpha) {
    if (blockIdx.x == 0 && threadIdx.x == 0) g_acc = 0.0;
    int w = (blockIdx.x * blockDim.x + threadIdx.x) >> 5;
    int lane = threadIdx.x & 31;
    if (w >= NN) return;
    float2 v = ((const float2*)(Z + (size_t)w * DD))[lane];
    float s = v.x + v.y;
    float sq = v.x * v.x + v.y * v.y;
#pragma unroll
    for (int off = 16; off; off >>= 1) {
        s  += __shfl_xor_sync(0xffffffffu, s, off);
        sq += __shfl_xor_sync(0xffffffffu, sq, off);
    }
    if (lane == 0) {
        g_pi[w] = 0.5f * (sq + 2.0f * EPSF * s + (float)DD * EPSF * EPSF);
        g_qa[2 * w]     = 0.5f * (sq - 2.0f * EPSF * s);
        g_qa[2 * w + 1] = alpha[w] * L2E;     // alpha in log2 units
    }
}

__device__ __forceinline__ uint32_t pack_bf16x2(float lo, float hi) {
    uint32_t r;
    asm("cvt.rn.bf16x2.f32 %0, %1, %2;" : "=r"(r) : "f"(hi), "f"(lo));
    return r;
}
__device__ __forceinline__ float sqrt_approx(float x) {
    float r; asm("sqrt.approx.f32 %0, %1;" : "=f"(r) : "f"(x)); return r;
}
__device__ __forceinline__ float ex2f(float x) {
    float r; asm("ex2.approx.f32 %0, %1;" : "=f"(r) : "f"(x)); return r;
}

// ---------------------------------------------------------------------------
// main: symmetric unordered pairs. Block (bi,bj) with bj>=2*bi covers
// I-rows [128bi,128bi+128) x J-cols [64bj,64bj+64). acc = d^2/2 via
// negated-Zj MMA with init 0.5pi+0.5q. One sqrt + both orientations.
// Diagonal excluded here; added analytically in finish.
// ---------------------------------------------------------------------------
__global__ __launch_bounds__(128) void lsm_main(const int* __restrict__ A,
                                                const float* __restrict__ Z) {
    const int bi = blockIdx.y, bj = blockIdx.x;
    if (bj < 2 * bi) return;
    extern __shared__ __align__(16) uint32_t smem[];
    uint32_t* s_zi = smem;                        // [128][PITCH_W]
    uint32_t* s_zj = smem + 128 * PITCH_W;        // [64][PITCH_W], negated
    float* s_pi = (float*)(s_zj + 64 * PITCH_W);  // [128] pi_half
    float* s_ay = s_pi + 128;                     // [128] alpha_i * L2E
    float* s_qa = s_ay + 128;                     // 64 float2 (q_half, qy)
    float* s_ws = s_qa + 128;                     // [4]

    const int tid = (int)threadIdx.x;
    const int wid = tid >> 5, lane = tid & 31;
    const int g = lane >> 2, t = lane & 3;
    const int wm = wid * 32;
    const bool strict = (bj >= 2 * bi + 2);

    // ---- small arrays ----
    s_pi[tid] = g_pi[bi * 128 + tid];
    s_ay[tid] = g_qa[2 * (bi * 128 + tid) + 1];
    if (tid < 64) ((float2*)s_qa)[tid] = ((const float2*)g_qa)[bj * 64 + tid];

    // ---- Z tiles (Zj negated) ----
    {
        const float4* src = (const float4*)(Z + (size_t)(bi * 128) * DD);
#pragma unroll
        for (int it = 0; it < 16; ++it) {
            int idx = it * 128 + tid;
            int r = idx >> 4, k4 = idx & 15;
            float4 v = src[(size_t)r * 16 + k4];
            *(uint2*)(s_zi + r * PITCH_W + k4 * 2) =
                make_uint2(pack_bf16x2(v.x, v.y), pack_bf16x2(v.z, v.w));
        }
        const float4* srcj = (const float4*)(Z + (size_t)(bj * 64) * DD);
#pragma unroll
        for (int it = 0; it < 8; ++it) {
            int idx = it * 128 + tid;
            int r = idx >> 4, k4 = idx & 15;
            float4 v = srcj[(size_t)r * 16 + k4];
            *(uint2*)(s_zj + r * PITCH_W + k4 * 2) =
                make_uint2(pack_bf16x2(v.x, v.y) ^ 0x80008000u,
                           pack_bf16x2(v.z, v.w) ^ 0x80008000u);
        }
    }
    __syncthreads();

    const float2* qaf2 = (const float2*)s_qa;

    // ---- a-fragments ----
    uint32_t a[4][2][4];
#pragma unroll
    for (int ks = 0; ks < 4; ++ks)
#pragma unroll
        for (int mf = 0; mf < 2; ++mf) {
            int r0 = wm + mf * 16 + g;
            const uint32_t* base = s_zi + ks * 8 + t;
            a[ks][mf][0] = base[r0 * PITCH_W];
            a[ks][mf][1] = base[(r0 + 8) * PITCH_W];
            a[ks][mf][2] = base[r0 * PITCH_W + 4];
            a[ks][mf][3] = base[(r0 + 8) * PITCH_W + 4];
        }

    // per-thread row constants + A pointers
    float pir[4], piy[4];
    int igr[4];
    const int2* ar[4];        // A[ig][jg..] row pointers (coalesced int2)
    const int* aj[4];         // A[.][ig] column bases: + jloc*NN
#pragma unroll
    for (int mf = 0; mf < 2; ++mf)
#pragma unroll
        for (int rs = 0; rs < 2; ++rs) {
            int r = mf * 2 + rs;
            int i_loc = wm + mf * 16 + rs * 8 + g;
            int ig = bi * 128 + i_loc;
            igr[r] = ig;
            pir[r] = s_pi[i_loc];
            piy[r] = s_ay[i_loc];
            ar[r] = (const int2*)(A + (size_t)ig * NN + bj * 64);
            aj[r] = A + (size_t)(bj * 64) * NN + ig;
        }

    float llA = 0.0f;    // sum of A * theta (log2 units), both orientations
    float llS = 0.0f;    // sum of softplus-linear terms
    float acc0[2][4], acc1[2][4];

#define DO_MMA(NF, ACC)                                                        \
    do {                                                                       \
        float qh0 = qaf2[(NF) * 8 + 2 * t].x;                                  \
        float qh1 = qaf2[(NF) * 8 + 2 * t + 1].x;                              \
        _Pragma("unroll")                                                      \
        for (int mf = 0; mf < 2; ++mf) {                                       \
            ACC[mf][0] = pir[mf * 2] + qh0;                                    \
            ACC[mf][1] = pir[mf * 2] + qh1;                                    \
            ACC[mf][2] = pir[mf * 2 + 1] + qh0;                                \
            ACC[mf][3] = pir[mf * 2 + 1] + qh1;                                \
        }                                                                      \
        _Pragma("unroll")                                                      \
        for (int ks = 0; ks < 4; ++ks) {                                       \
            int c0 = (NF) * 8 + g;                                             \
            uint32_t b0 = s_zj[c0 * PITCH_W + ks * 8 + t];                     \
            uint32_t b1 = s_zj[c0 * PITCH_W + ks * 8 + t + 4];                 \
            _Pragma("unroll")                                                  \
            for (int mf = 0; mf < 2; ++mf) {                                   \
                asm volatile(                                                  \
                    "mma.sync.aligned.m16n8k16.row.col.f32.bf16.bf16.f32 "     \
                    "{%0,%1,%2,%3}, {%4,%5,%6,%7}, {%8,%9}, {%0,%1,%2,%3};"    \
                    : "+f"(ACC[mf][0]), "+f"(ACC[mf][1]),                      \
                      "+f"(ACC[mf][2]), "+f"(ACC[mf][3])                       \
                    : "r"(a[ks][mf][0]), "r"(a[ks][mf][1]),                    \
                      "r"(a[ks][mf][2]), "r"(a[ks][mf][3]),                    \
                      "r"(b0), "r"(b1));                                       \
            }                                                                  \
        }                                                                      \
    } while (0)

    // MASKED is a compile-time 0/1; slow path recomputes from live ACC.
#define DO_EPI(NF, ACC, MASKED)                                                \
    do {                                                                       \
        float umax = 0.0f;                                                     \
        float qy0 = qaf2[(NF) * 8 + 2 * t].y;                                  \
        float qy1 = qaf2[(NF) * 8 + 2 * t + 1].y;                              \
        int jl0 = (NF) * 8 + 2 * t;                                            \
        _Pragma("unroll")                                                      \
        for (int mf = 0; mf < 2; ++mf)                                         \
            _Pragma("unroll")                                                  \
            for (int rs = 0; rs < 2; ++rs) {                                   \
                int r = mf * 2 + rs;                                           \
                int2 a2 = ar[r][(NF) * 4 + t];                                 \
                int aj0 = aj[r][(size_t)jl0 * NN];                             \
                int aj1 = aj[r][(size_t)(jl0 + 1) * NN];                       \
                bool v0 = true, v1 = true;                                     \
                if (MASKED) {                                                  \
                    v0 = (bj * 64 + jl0) > igr[r];                             \
                    v1 = (bj * 64 + jl0 + 1) > igr[r];                         \
                }                                                              \
                float z0 = sqrt_approx(fmaxf(ACC[mf][rs * 2 + 0], 0.0f));      \
                float z1 = sqrt_approx(fmaxf(ACC[mf][rs * 2 + 1], 0.0f));      \
                float ta0 = fmaf(z0, -SQRT2_L2E, qy0);                         \
                float ta1 = fmaf(z1, -SQRT2_L2E, qy1);                         \
                float tb0 = fmaf(z0, -SQRT2_L2E, piy[r]);                      \
                float tb1 = fmaf(z1, -SQRT2_L2E, piy[r]);                      \
                float ua0 = ex2f(ta0), ua1 = ex2f(ta1);                        \
                float ub0 = ex2f(tb0), ub1 = ex2f(tb1);                        \
                if (MASKED) {                                                  \
                    if (!v0) { ua0 = 0.0f; ub0 = 0.0f; }                       \
                    if (!v1) { ua1 = 0.0f; ub1 = 0.0f; }                       \
                }                                                              \
                llS += (ua0 + ub0) + (ua1 + ub1);                              \
                umax = fmaxf(umax, fmaxf(fmaxf(ua0, ub0), fmaxf(ua1, ub1)));   \
                if (a2.x && v0) llA += ta0;                                    \
                if (a2.y && v1) llA += ta1;                                    \
                if (aj0 && v0) llA += tb0;                                     \
                if (aj1 && v1) llA += tb1;                                     \
            }                                                                  \
        if (__any_sync(0xffffffffu, umax > T_U)) {  /* rare */                 \
            _Pragma("unroll")                                                  \
            for (int mf = 0; mf < 2; ++mf)                                     \
                _Pragma("unroll")                                              \
                for (int rs = 0; rs < 2; ++rs)                                 \
                    _Pragma("unroll")                                          \
                    for (int c = 0; c < 2; ++c) {                              \
                        int r = mf * 2 + rs;                                   \
                        bool vv = true;                                        \
                        if (MASKED) vv = (bj * 64 + jl0 + c) > igr[r];         \
                        if (!vv) continue;                                     \
                        float z = sqrt_approx(                                 \
                            fmaxf(ACC[mf][rs * 2 + c], 0.0f));                 \
                        float ta = fmaf(z, -SQRT2_L2E, c ? qy1 : qy0);         \
                        float tb = fmaf(z, -SQRT2_L2E, piy[r]);                \
                        float ua = ex2f(ta), ub = ex2f(tb);                    \
                        if (ua > T_U) llS += __logf(1.0f + ua) - ua;           \
                        if (ub > T_U) llS += __logf(1.0f + ub) - ub;           \
                    }                                                          \
        }                                                                      \
    } while (0)

#define PIPELINE(MASKED)                                                       \
    DO_MMA(0, acc0);                                                           \
    DO_MMA(1, acc1);  DO_EPI(0, acc0, MASKED);                                 \
    DO_MMA(2, acc0);  DO_EPI(1, acc1, MASKED);                                 \
    DO_MMA(3, acc1);  DO_EPI(2, acc0, MASKED);                                 \
    DO_MMA(4, acc0);  DO_EPI(3, acc1, MASKED);                                 \
    DO_MMA(5, acc1);  DO_EPI(4, acc0, MASKED);                                 \
    DO_MMA(6, acc0);  DO_EPI(5, acc1, MASKED);                                 \
    DO_MMA(7, acc1);  DO_EPI(6, acc0, MASKED);                                 \
    DO_EPI(7, acc1, MASKED);

    if (strict) { PIPELINE(0) } else { PIPELINE(1) }

    float ll = 0.5f * (fmaf(llA, LN2, -llS));

#pragma unroll
    for (int off = 16; off; off >>= 1) ll += __shfl_xor_sync(0xffffffffu, ll, off);
    if (lane == 0) s_ws[wid] = ll;
    __syncthreads();
    if (tid == 0)
        atomicAdd(&g_acc, (double)(s_ws[0] + s_ws[1] + s_ws[2] + s_ws[3]));
}

// ---------------------------------------------------------------------------
// finish: analytic diagonal 0.5 * sum_i A_ii * (alpha_i - 8e-6); emit scalar.
// ---------------------------------------------------------------------------
__global__ void finish_kernel(const int* __restrict__ A, float* out) {
    __shared__ float sh[8];
    int tid = (int)threadIdx.x;
    float p = 0.0f;
    for (int i = tid; i < NN; i += 256)
        if (A[(size_t)i * NN + i])
            p += g_qa[2 * i + 1] * LN2 - 8.0f * EPSF;
#pragma unroll
    for (int off = 16; off; off >>= 1) p += __shfl_xor_sync(0xffffffffu, p, off);
    if ((tid & 31) == 0) sh[tid >> 5] = p;
    __syncthreads();
    if (tid == 0) {
        float d = 0.0f;
#pragma unroll
        for (int w = 0; w < 8; ++w) d += sh[w];
        out[0] = (float)(g_acc + 0.5 * (double)d);
    }
}

// ---------------------------------------------------------------------------
extern "C" void kernel_launch(void* const* d_in, const int* in_sizes, int n_in,
                              void* d_out, int out_size) {
    const int* A = nullptr;
    const float* alpha = nullptr;
    const float* Z = nullptr;
    for (int i = 0; i < n_in; ++i) {
        if (in_sizes[i] == NN) alpha = (const float*)d_in[i];
        else if (in_sizes[i] == NN * DD) Z = (const float*)d_in[i];
        else A = (const int*)d_in[i];
    }

    const int smem_bytes = (128 * PITCH_W + 64 * PITCH_W + 128 + 128 + 128 + 4) * 4;
    cudaFuncSetAttribute(lsm_main, cudaFuncAttributeMaxDynamicSharedMemorySize,
                         smem_bytes);

    prep_kernel<<<(NN * 32 + 255) / 256, 256>>>(Z, alpha);
    dim3 grid(NN / 64, NN / 128);
    lsm_main<<<grid, 128, smem_bytes>>>(A, Z);
    finish_kernel<<<1, 256>>>(A, (float*)d_out);
}